// round 15
// baseline (speedup 1.0000x reference)
#include <cuda_runtime.h>
#include <cuda_bf16.h>
#include <cuda_fp16.h>
#include <cstdint>

// SorscherRNN on mma.sync, fp16 asymmetric split (A hi+lo fp16, W single fp16).
// R15 = R14 with the 100 step launches fused into ONE persistent kernel:
//  - continuous 3-slot mbar ring over sg = 8t+s (no per-step pipeline refill)
//  - split W/A arrivals (mbar count=2): W prefetches across step boundary,
//    A gated on producer epilogues via monotonic ecnt counters
//  - distributed 4-way reduction + epilogue kept from R14.

#define NG 4096
#define NP 512
#define BB 64
#define TT 100

// step kernel: stage = W 32KB | A 32KB ([Whi0|Whi1] | [Ahi0|Alo0|Ahi1|Alo1])
#define NSTG 8
#define STG_BYTES 65536u
#define OW 0u
#define OA 32768u
#define SMEM_STEP (1024 + 3 * 65536)

// decode: stage = A 32KB (hi|lo) | W 8KB
#define DSTG 40960u
#define D_OAH 0u
#define D_OAL 16384u
#define D_OWH 32768u
#define SMEM_DEC (1024 + 4 * 40960)

typedef unsigned long long ull;

// ---------------- device scratch (allocation-free) ----------------
__device__ __align__(16) unsigned char d_wtile[4ull * 32 * 16 * 16384];  // 32MB W_hh fp16 tiled
__device__ __align__(16) unsigned char d_aslab[2ull * 4 * 16 * 16384];   // 2MB A hi|lo, dbl-buf
__device__ __align__(16) unsigned char d_gslab[50ull * 64 * 32768];      // 100MB g hi|lo tiled
__device__ __align__(16) unsigned char d_wdtile[8ull * 64 * 8192];       // 4MB W_dec fp16 tiled
__device__ float d_va[BB * NG], d_zp[BB * NG];
__device__ float d_part[4ull * BB * NG];  // 4 split-K partial slabs
__device__ int d_cnt[64];  // [0..31]=pcnt (partials), [32..63]=ecnt (A published); monotonic

// ---------------- helpers ----------------
__device__ __forceinline__ uint32_t smem_u32(const void* p) {
  uint32_t a;
  asm("{ .reg .u64 t; cvta.to.shared.u64 t, %1; cvt.u32.u64 %0, t; }" : "=r"(a) : "l"(p));
  return a;
}

#define MBAR_INIT(a, c) asm volatile("mbarrier.init.shared.b64 [%0], %1;" :: "r"(a), "r"(c) : "memory")
#define MBAR_EXPECT_TX(a, n) \
  asm volatile("mbarrier.arrive.expect_tx.shared.b64 _, [%0], %1;" :: "r"(a), "r"(n) : "memory")
__device__ __forceinline__ void mbar_wait(uint32_t a, uint32_t par) {
  asm volatile(
      "{ .reg .pred P;\n"
      "WL%=: mbarrier.try_wait.parity.acquire.cta.shared::cta.b64 P, [%0], %1, 0x989680;\n"
      "@P bra WD%=;\n"
      "bra WL%=;\n"
      "WD%=: }"
      :: "r"(a), "r"(par) : "memory");
}
#define BULK_G2S(dst, src, sz, mb) \
  asm volatile("cp.async.bulk.shared::cta.global.mbarrier::complete_tx::bytes [%0], [%1], %2, [%3];" \
               :: "r"(dst), "l"(src), "r"(sz), "r"(mb) : "memory")

#define LDSM4(r0, r1, r2, r3, a) \
  asm volatile("ldmatrix.sync.aligned.m8n8.x4.shared.b16 {%0,%1,%2,%3}, [%4];" \
               : "=r"(r0), "=r"(r1), "=r"(r2), "=r"(r3) : "r"(a))

#define MMAH(d, a, b0, b1) \
  asm volatile("mma.sync.aligned.m16n8k16.row.col.f32.f16.f16.f32 " \
               "{%0,%1,%2,%3}, {%4,%5,%6,%7}, {%8,%9}, {%0,%1,%2,%3};" \
               : "+f"((d)[0]), "+f"((d)[1]), "+f"((d)[2]), "+f"((d)[3]) \
               : "r"((a)[0]), "r"((a)[1]), "r"((a)[2]), "r"((a)[3]), "r"(b0), "r"(b1))

__device__ __forceinline__ void split2h(float a, float b, uint32_t& hi, uint32_t& lo) {
  __half ha = __float2half_rn(a), hb = __float2half_rn(b);
  __half la = __float2half_rn(a - __half2float(ha));
  __half lb = __float2half_rn(b - __half2float(hb));
  __half2 H(ha, hb), L(la, lb);
  hi = *(uint32_t*)&H;
  lo = *(uint32_t*)&L;
}

// ---------------- prep kernels ----------------
__global__ void zero_state_kernel() {
  int i = blockIdx.x * blockDim.x + threadIdx.x;
  int stride = gridDim.x * blockDim.x;
  for (int k = i; k < BB * NG; k += stride) { d_va[k] = 0.0f; d_zp[k] = 0.0f; }
  if (blockIdx.x == 0 && threadIdx.x < 64) d_cnt[threadIdx.x] = 0;
}

__global__ void convert_whh(const float* __restrict__ W) {
  int i = blockIdx.x * blockDim.x + threadIdx.x;
  int stride = gridDim.x * blockDim.x;
  for (; i < NG * NG / 8; i += stride) {
    int n = i >> 9, k = (i & 511) << 3;
    const float4* s = (const float4*)(W + (long)n * NG + k);
    float4 x = s[0], y = s[1];
    __half2 h0(__float2half_rn(x.x), __float2half_rn(x.y));
    __half2 h1(__float2half_rn(x.z), __float2half_rn(x.w));
    __half2 h2(__float2half_rn(y.x), __float2half_rn(y.y));
    __half2 h3(__float2half_rn(y.z), __float2half_rn(y.w));
    uint4 u = make_uint4(*(uint32_t*)&h0, *(uint32_t*)&h1, *(uint32_t*)&h2, *(uint32_t*)&h3);
    int by = k >> 10, sg = (k & 1023) >> 6, ch = (k & 63) >> 3;
    int bx = n >> 7, r = n & 127;
    long off = (long)((by * 32 + bx) * 16 + sg) * 16384 + r * 128 + ((ch ^ (r & 7)) << 4);
    *(uint4*)(d_wtile + off) = u;
  }
}

__global__ void convert_wdec(const float* __restrict__ W) {
  int i = blockIdx.x * blockDim.x + threadIdx.x;
  int stride = gridDim.x * blockDim.x;
  for (; i < NP * NG / 8; i += stride) {
    int n = i >> 9, k = (i & 511) << 3;
    const float4* s = (const float4*)(W + (long)n * NG + k);
    float4 x = s[0], y = s[1];
    __half2 h0(__float2half_rn(x.x), __float2half_rn(x.y));
    __half2 h1(__float2half_rn(x.z), __float2half_rn(x.w));
    __half2 h2(__float2half_rn(y.x), __float2half_rn(y.y));
    __half2 h3(__float2half_rn(y.z), __float2half_rn(y.w));
    uint4 u = make_uint4(*(uint32_t*)&h0, *(uint32_t*)&h1, *(uint32_t*)&h2, *(uint32_t*)&h3);
    int nx = n >> 6, rn = n & 63;
    int kt = k >> 6, ch = (k & 63) >> 3;
    long off = (long)(nx * 64 + kt) * 8192 + rn * 128 + ((ch ^ (rn & 7)) << 4);
    *(uint4*)(d_wdtile + off) = u;
  }
}

// h0 = p0 @ W_init^T  -> A-slab parity 0 (fp16 hi|lo, tiled/swizzled)
__global__ void h0_kernel(const float* __restrict__ p0, const float* __restrict__ Wi) {
  __shared__ __align__(16) float hs[32][68];
  __shared__ __align__(16) float ws[32][34];
  const int tid = threadIdx.x;
  const int tx = tid & 15, ty = tid >> 4, lk = tid & 31, lr = tid >> 5;
  const int nb = blockIdx.x * 32;
  float acc[4][2];
#pragma unroll
  for (int i = 0; i < 4; i++) { acc[i][0] = 0.f; acc[i][1] = 0.f; }
  float rh[8], rw[4];
#pragma unroll
  for (int i = 0; i < 8; i++) rh[i] = p0[(lr + 8 * i) * NP + lk];
#pragma unroll
  for (int i = 0; i < 4; i++) rw[i] = Wi[(nb + lr + 8 * i) * NP + lk];
  for (int k0 = 0; k0 < NP; k0 += 32) {
#pragma unroll
    for (int i = 0; i < 8; i++) hs[lk][lr + 8 * i] = rh[i];
#pragma unroll
    for (int i = 0; i < 4; i++) ws[lk][lr + 8 * i] = rw[i];
    __syncthreads();
    int k1 = k0 + 32;
    if (k1 < NP) {
#pragma unroll
      for (int i = 0; i < 8; i++) rh[i] = p0[(lr + 8 * i) * NP + k1 + lk];
#pragma unroll
      for (int i = 0; i < 4; i++) rw[i] = Wi[(nb + lr + 8 * i) * NP + k1 + lk];
    }
#pragma unroll
    for (int k = 0; k < 32; k++) {
      float4 hv = *(const float4*)&hs[k][ty * 4];
      float2 wv = *(const float2*)&ws[k][tx * 2];
      acc[0][0] += hv.x * wv.x; acc[0][1] += hv.x * wv.y;
      acc[1][0] += hv.y * wv.x; acc[1][1] += hv.y * wv.y;
      acc[2][0] += hv.z * wv.x; acc[2][1] += hv.z * wv.y;
      acc[3][0] += hv.w * wv.x; acc[3][1] += hv.w * wv.y;
    }
    __syncthreads();
  }
  const int m0 = ty * 4;
  const int n0 = nb + tx * 2;
  const int byn = n0 >> 10, sn = (n0 & 1023) >> 6, ch = (n0 & 63) >> 3;
#pragma unroll
  for (int i = 0; i < 4; i++) {
    uint32_t hi, lo;
    split2h(acc[i][0], acc[i][1], hi, lo);
    int m = m0 + i;
    long off = (long)(byn * 16 + sn) * 16384 + m * 128 + ((ch ^ (m & 7)) << 4) + (n0 & 7) * 2;
    *(uint32_t*)(d_aslab + off) = hi;
    *(uint32_t*)(d_aslab + off + 8192) = lo;
  }
}

// ---------------- persistent step kernel: all 100 steps ----------------
// grid (32, 4): bx = n-tile (128 cols), by = k-chunk (1024).
// All CTAs write partials; each reduces its own 32-col quarter + epilogue.
__global__ void __launch_bounds__(256, 1) rnn_persistent(
    const float* __restrict__ v, const float* __restrict__ Wih) {
  extern __shared__ __align__(1024) char smem[];
  const uint32_t sb = smem_u32(smem);
  const uint32_t mb = sb;
  const uint32_t buf = sb + 1024;
  const int tid = threadIdx.x;
  const int bx = blockIdx.x, by = blockIdx.y;
  const int nb = bx * 128;

  if (tid == 0) {
#pragma unroll
    for (int i = 0; i < 3; i++) MBAR_INIT(mb + 8 * i, 2);  // 2 arrives: W + A expect_tx
  }
  __syncthreads();

  const ull wbase = (ull)__cvta_generic_to_global(d_wtile) +
                    (ull)((by * 32 + bx) * 16) * 16384ull;
  const ull aslab = (ull)__cvta_generic_to_global(d_aslab);

  auto issueW = [&](int sg) {
    const int slot = sg % 3;
    const uint32_t m = mb + slot * 8;
    MBAR_EXPECT_TX(m, 32768u);
    BULK_G2S(buf + (uint32_t)slot * STG_BYTES + OW,
             wbase + (ull)(sg & 7) * 32768ull, 32768u, m);
  };
  auto issueA = [&](int sg) {
    const int slot = sg % 3;
    const int t = sg >> 3, s = sg & 7;
    const uint32_t m = mb + slot * 8;
    const ull abase = aslab + (ull)(((t & 1) * 4 + by) * 16) * 16384ull;
    MBAR_EXPECT_TX(m, 32768u);
    BULK_G2S(buf + (uint32_t)slot * STG_BYTES + OA,
             abase + (ull)s * 32768ull, 32768u, m);
  };

  if (tid == 0) { issueW(0); issueA(0); issueW(1); issueA(1); }

  const int lane = tid & 31, warp = tid >> 5;
  const int wm = warp & 1, wn = warp >> 1;          // 2m x 4n warps
  const int mA0 = wm * 32 + (lane & 15);            // < 64
  const int nB0 = wn * 32 + (lane & 15);            // < 128
  const int halfk = lane >> 4;
  const uint32_t aA0 = (uint32_t)mA0 * 128, aA1 = aA0 + 16 * 128;
  const uint32_t aB0 = (uint32_t)nB0 * 128, aB1 = aB0 + 16 * 128;
  const uint32_t swA = (uint32_t)(mA0 & 7), swB = (uint32_t)(nB0 & 7);
  const int r_ = lane >> 2, c_ = (lane & 3) * 2;
  const float2* wih2 = (const float2*)Wih;

  for (int t = 0; t < TT; t++) {
    float acc[2][4][4];
#pragma unroll
    for (int mi = 0; mi < 2; mi++)
#pragma unroll
      for (int sl = 0; sl < 4; sl++)
#pragma unroll
        for (int f = 0; f < 4; f++) acc[mi][sl][f] = 0.0f;

    for (int s = 0; s < NSTG; s++) {
      const int sg = t * 8 + s;
      mbar_wait(mb + (sg % 3) * 8, (uint32_t)((sg / 3) & 1));
      const uint32_t st = buf + (uint32_t)(sg % 3) * STG_BYTES;
#pragma unroll
      for (int k16 = 0; k16 < 8; k16++) {
        const uint32_t sub = (uint32_t)(k16 >> 2) * 16384u;
        const uint32_t ch = (uint32_t)((k16 & 3) * 2 + halfk);
        const uint32_t xoA = (ch ^ swA) << 4;
        const uint32_t xoB = (ch ^ swB) << 4;
        uint32_t Ah[2][4], Al[2][4], Wb[2][4];
        LDSM4(Ah[0][0], Ah[0][1], Ah[0][2], Ah[0][3], st + OA + sub + aA0 + xoA);
        LDSM4(Ah[1][0], Ah[1][1], Ah[1][2], Ah[1][3], st + OA + sub + aA1 + xoA);
        LDSM4(Al[0][0], Al[0][1], Al[0][2], Al[0][3], st + OA + sub + 8192 + aA0 + xoA);
        LDSM4(Al[1][0], Al[1][1], Al[1][2], Al[1][3], st + OA + sub + 8192 + aA1 + xoA);
        LDSM4(Wb[0][0], Wb[0][1], Wb[0][2], Wb[0][3], st + OW + sub + aB0 + xoB);
        LDSM4(Wb[1][0], Wb[1][1], Wb[1][2], Wb[1][3], st + OW + sub + aB1 + xoB);
#pragma unroll
        for (int mi = 0; mi < 2; mi++)
#pragma unroll
          for (int bb = 0; bb < 2; bb++)
#pragma unroll
            for (int j = 0; j < 2; j++)
              MMAH(acc[mi][bb * 2 + j], Ah[mi], Wb[bb][j], Wb[bb][j + 2]);
#pragma unroll
        for (int mi = 0; mi < 2; mi++)
#pragma unroll
          for (int bb = 0; bb < 2; bb++)
#pragma unroll
            for (int j = 0; j < 2; j++)
              MMAH(acc[mi][bb * 2 + j], Al[mi], Wb[bb][j], Wb[bb][j + 2]);
      }
      __syncthreads();
      if (tid == 0) {
        const int sgn = sg + 2;
        if (sgn < TT * 8) {
          issueW(sgn);
          if ((sgn >> 3) == t) issueA(sgn);  // cross-boundary A deferred below
        }
      }
    }

    // ---- write own partial slab ----
    {
      float* pp = d_part + (long)by * (BB * NG);
#pragma unroll
      for (int mi = 0; mi < 2; mi++)
#pragma unroll
        for (int bb = 0; bb < 2; bb++)
#pragma unroll
          for (int j = 0; j < 2; j++)
#pragma unroll
            for (int rr = 0; rr < 2; rr++) {
              int m = wm * 32 + mi * 16 + r_ + rr * 8;
              int n = nb + wn * 32 + bb * 16 + j * 8 + c_;
              *(float2*)&d_part[(long)by * (BB * NG) + m * NG + n] =
                  make_float2(acc[mi][bb * 2 + j][rr * 2], acc[mi][bb * 2 + j][rr * 2 + 1]);
            }
      (void)pp;
    }
    __threadfence();
    __syncthreads();
    if (tid == 0) {
      atomicAdd(&d_cnt[bx], 1);
      while (atomicAdd(&d_cnt[bx], 0) < 4 * (t + 1)) __nanosleep(32);
    }
    __syncthreads();
    __threadfence();

    // ---- distributed reduction + RNN epilogue: this CTA owns 32 cols ----
    {
      const int p1 = (t + 1) & 1;
      const int nq = nb + by * 32;
#pragma unroll
      for (int p = 0; p < 4; p++) {
        const int m = warp * 8 + p * 2 + (lane >> 4);
        const int n0 = nq + (lane & 15) * 2;
        const int idx = m * NG + n0;
        float2 q0 = *(const float2*)&d_part[idx];
        float2 q1 = *(const float2*)&d_part[(long)BB * NG + idx];
        float2 q2 = *(const float2*)&d_part[2l * BB * NG + idx];
        float2 q3 = *(const float2*)&d_part[3l * BB * NG + idx];
        const float v0 = v[(m * TT + t) * 2 + 0];
        const float v1 = v[(m * TT + t) * 2 + 1];
        float2 w0 = wih2[n0], w1 = wih2[n0 + 1];
        float z0 = ((q0.x + q1.x) + q2.x) + q3.x + v0 * w0.x + v1 * w0.y;
        float z1 = ((q0.y + q1.y) + q2.y) + q3.y + v0 * w1.x + v1 * w1.y;
        float2 va = *(const float2*)&d_va[idx];
        float2 zp = *(const float2*)&d_zp[idx];
        z0 -= 0.1f * va.x;
        z1 -= 0.1f * va.y;
        *(float2*)&d_va[idx] = make_float2(va.x + 0.9f * (zp.x - va.x),
                                           va.y + 0.9f * (zp.y - va.y));
        *(float2*)&d_zp[idx] = make_float2(z0, z1);
        float s0 = fmaxf(z0, 0.0f), s1 = fmaxf(z1, 0.0f);
        uint32_t hi, lo;
        split2h(s0, s1, hi, lo);
        const int m_dec = m * TT + t;
        const int mt = m_dec >> 7, rdec = m_dec & 127;
        const int kt = n0 >> 6, chn = (n0 & 63) >> 3;
        long goff = (long)(mt * 64 + kt) * 32768 + rdec * 128 +
                    ((chn ^ (rdec & 7)) << 4) + (n0 & 7) * 2;
        *(uint32_t*)(d_gslab + goff) = hi;
        *(uint32_t*)(d_gslab + goff + 16384) = lo;
        const int byn = n0 >> 10, sn = (n0 & 1023) >> 6;
        long off = (long)((p1 * 4 + byn) * 16 + sn) * 16384 + m * 128 +
                   ((chn ^ (m & 7)) << 4) + (n0 & 7) * 2;
        *(uint32_t*)(d_aslab + off) = hi;
        *(uint32_t*)(d_aslab + off + 8192) = lo;
      }
    }
    __threadfence();
    __syncthreads();
    if (tid == 0) {
      atomicAdd(&d_cnt[32 + bx], 1);
      if (t + 1 < TT) {
        // gate: ALL A-source CTAs for this by-group must have published step-t A
#pragma unroll
        for (int s = 0; s < 8; s++) {
          while (atomicAdd(&d_cnt[32 + by * 8 + s], 0) < 4 * (t + 1)) __nanosleep(32);
        }
        __threadfence();
        const int b0 = (t + 1) * 8;
        issueA(b0); issueA(b0 + 1);
      }
    }
  }
}

// ---------------- decode: bulk-fed pipeline, 2 MMA passes (unchanged) ----------------
__global__ void __launch_bounds__(256, 1) decode_gemm(float* __restrict__ outp) {
  extern __shared__ __align__(1024) char smem[];
  const uint32_t sb = smem_u32(smem);
  const uint32_t mb = sb;
  const uint32_t buf = sb + 1024;
  const int tid = threadIdx.x;
  const int nx = blockIdx.x, mt = blockIdx.y;

  if (tid == 0) {
#pragma unroll
    for (int i = 0; i < 4; i++) MBAR_INIT(mb + 8 * i, 1);
  }
  __syncthreads();

  const ull gbase = (ull)__cvta_generic_to_global(d_gslab) + (ull)(mt * 64) * 32768ull;
  const ull wbase = (ull)__cvta_generic_to_global(d_wdtile) + (ull)(nx * 64) * 8192ull;

  auto issue = [&](int s) {
    const uint32_t st = buf + (uint32_t)(s & 3) * DSTG;
    const uint32_t m = mb + (s & 3) * 8;
    MBAR_EXPECT_TX(m, DSTG);
    BULK_G2S(st + D_OAH, gbase + (ull)s * 32768ull, 32768u, m);
    BULK_G2S(st + D_OWH, wbase + (ull)s * 8192ull, 8192u, m);
  };
  if (tid == 0) { issue(0); issue(1); issue(2); }

  const int lane = tid & 31, warp = tid >> 5;
  const int wm = warp & 3, wn = warp >> 2;
  const int mA0 = wm * 32 + (lane & 15);
  const int nB0 = wn * 32 + (lane & 15);
  const int halfk = lane >> 4;
  const uint32_t aA0 = (uint32_t)mA0 * 128, aA1 = aA0 + 16 * 128;
  const uint32_t aB0 = (uint32_t)nB0 * 128, aB1 = aB0 + 16 * 128;
  const uint32_t swA = (uint32_t)(mA0 & 7), swB = (uint32_t)(nB0 & 7);

  float acc[2][4][4];
#pragma unroll
  for (int mi = 0; mi < 2; mi++)
#pragma unroll
    for (int sl = 0; sl < 4; sl++)
#pragma unroll
      for (int f = 0; f < 4; f++) acc[mi][sl][f] = 0.0f;

  for (int s = 0; s < 64; s++) {
    mbar_wait(mb + (s & 3) * 8, (uint32_t)((s >> 2) & 1));
    const uint32_t st = buf + (uint32_t)(s & 3) * DSTG;
#pragma unroll
    for (int k16 = 0; k16 < 4; k16++) {
      const uint32_t ch = (uint32_t)(k16 * 2 + halfk);
      const uint32_t xoA = (ch ^ swA) << 4;
      const uint32_t xoB = (ch ^ swB) << 4;
      uint32_t Ah[2][4], Al[2][4], Wb[2][4];
      LDSM4(Ah[0][0], Ah[0][1], Ah[0][2], Ah[0][3], st + D_OAH + aA0 + xoA);
      LDSM4(Ah[1][0], Ah[1][1], Ah[1][2], Ah[1][3], st + D_OAH + aA1 + xoA);
      LDSM4(Al[0][0], Al[0][1], Al[0][2], Al[0][3], st + D_OAL + aA0 + xoA);
      LDSM4(Al[1][0], Al[1][1], Al[1][2], Al[1][3], st + D_OAL + aA1 + xoA);
      LDSM4(Wb[0][0], Wb[0][1], Wb[0][2], Wb[0][3], st + D_OWH + aB0 + xoB);
      LDSM4(Wb[1][0], Wb[1][1], Wb[1][2], Wb[1][3], st + D_OWH + aB1 + xoB);
#pragma unroll
      for (int mi = 0; mi < 2; mi++)
#pragma unroll
        for (int bb = 0; bb < 2; bb++)
#pragma unroll
          for (int j = 0; j < 2; j++)
            MMAH(acc[mi][bb * 2 + j], Ah[mi], Wb[bb][j], Wb[bb][j + 2]);
#pragma unroll
      for (int mi = 0; mi < 2; mi++)
#pragma unroll
        for (int bb = 0; bb < 2; bb++)
#pragma unroll
          for (int j = 0; j < 2; j++)
            MMAH(acc[mi][bb * 2 + j], Al[mi], Wb[bb][j], Wb[bb][j + 2]);
    }
    __syncthreads();
    if (tid == 0 && s + 3 < 64) issue(s + 3);
  }

  const int r_ = lane >> 2, c_ = (lane & 3) * 2;
#pragma unroll
  for (int mi = 0; mi < 2; mi++)
#pragma unroll
    for (int bb = 0; bb < 2; bb++)
#pragma unroll
      for (int j = 0; j < 2; j++)
#pragma unroll
        for (int rr = 0; rr < 2; rr++) {
          long m = (long)mt * 128 + wm * 32 + mi * 16 + r_ + rr * 8;
          int n = nx * 64 + wn * 32 + bb * 16 + j * 8 + c_;
          *(float2*)&outp[m * NP + n] =
              make_float2(acc[mi][bb * 2 + j][rr * 2], acc[mi][bb * 2 + j][rr * 2 + 1]);
        }
}

// ---------------- launch ----------------
extern "C" void kernel_launch(void* const* d_in, const int* in_sizes, int n_in,
                              void* d_out, int out_size) {
  const float* v      = (const float*)d_in[0];
  const float* p0     = (const float*)d_in[1];
  const float* W_init = (const float*)d_in[2];
  const float* W_ih   = (const float*)d_in[3];
  const float* W_hh   = (const float*)d_in[4];
  const float* W_dec  = (const float*)d_in[5];
  float* out = (float*)d_out;

  cudaFuncSetAttribute(rnn_persistent, cudaFuncAttributeMaxDynamicSharedMemorySize, SMEM_STEP);
  cudaFuncSetAttribute(decode_gemm, cudaFuncAttributeMaxDynamicSharedMemorySize, SMEM_DEC);

  convert_whh<<<2048, 256>>>(W_hh);
  convert_wdec<<<256, 256>>>(W_dec);
  zero_state_kernel<<<128, 256>>>();
  h0_kernel<<<128, 256>>>(p0, W_init);

  rnn_persistent<<<dim3(32, 4), 256, SMEM_STEP>>>(v, W_ih);

  decode_gemm<<<dim3(8, 50), 256, SMEM_DEC>>>(out);
}

// round 16
// speedup vs baseline: 1.1039x; 1.1039x over previous
#include <cuda_runtime.h>
#include <cuda_bf16.h>
#include <cuda_fp16.h>
#include <cstdint>

// SorscherRNN on mma.sync, fp16 asymmetric split (A hi+lo fp16, W single fp16).
// R16 = R14 (best: per-step launches, KC=128 stages, distributed 4-way
// reduction+epilogue) + manual software pipelining of ldmatrix fragment loads
// (double-buffered fragments; LDSM(k16+1) issued before MMAs(k16)) so the
// smem port and tensor pipe overlap instead of serializing.

#define NG 4096
#define NP 512
#define BB 64
#define TT 100

// step kernel: stage = W 32KB | A 32KB ([Whi0|Whi1] | [Ahi0|Alo0|Ahi1|Alo1])
#define NSTG 8
#define STG_BYTES 65536u
#define OW 0u
#define OA 32768u
#define SMEM_STEP (1024 + 3 * 65536)

// decode: stage = A 32KB (hi|lo) | W 8KB
#define DSTG 40960u
#define D_OAH 0u
#define D_OAL 16384u
#define D_OWH 32768u
#define SMEM_DEC (1024 + 4 * 40960)

typedef unsigned long long ull;

// ---------------- device scratch (allocation-free) ----------------
__device__ __align__(16) unsigned char d_wtile[4ull * 32 * 16 * 16384];  // 32MB W_hh fp16 tiled
__device__ __align__(16) unsigned char d_aslab[2ull * 4 * 16 * 16384];   // 2MB A hi|lo, dbl-buf
__device__ __align__(16) unsigned char d_gslab[50ull * 64 * 32768];      // 100MB g hi|lo tiled
__device__ __align__(16) unsigned char d_wdtile[8ull * 64 * 8192];       // 4MB W_dec fp16 tiled
__device__ float d_va[BB * NG], d_zp[BB * NG];
__device__ float d_part[4ull * BB * NG];  // 4 split-K partial slabs
__device__ int d_cnt[32];                 // monotonic per-n-tile arrival counters

// ---------------- helpers ----------------
__device__ __forceinline__ uint32_t smem_u32(const void* p) {
  uint32_t a;
  asm("{ .reg .u64 t; cvta.to.shared.u64 t, %1; cvt.u32.u64 %0, t; }" : "=r"(a) : "l"(p));
  return a;
}

#define MBAR_INIT(a, c) asm volatile("mbarrier.init.shared.b64 [%0], %1;" :: "r"(a), "r"(c) : "memory")
#define MBAR_EXPECT_TX(a, n) \
  asm volatile("mbarrier.arrive.expect_tx.shared.b64 _, [%0], %1;" :: "r"(a), "r"(n) : "memory")
__device__ __forceinline__ void mbar_wait(uint32_t a, uint32_t par) {
  asm volatile(
      "{ .reg .pred P;\n"
      "WL%=: mbarrier.try_wait.parity.acquire.cta.shared::cta.b64 P, [%0], %1, 0x989680;\n"
      "@P bra WD%=;\n"
      "bra WL%=;\n"
      "WD%=: }"
      :: "r"(a), "r"(par) : "memory");
}
#define BULK_G2S(dst, src, sz, mb) \
  asm volatile("cp.async.bulk.shared::cta.global.mbarrier::complete_tx::bytes [%0], [%1], %2, [%3];" \
               :: "r"(dst), "l"(src), "r"(sz), "r"(mb) : "memory")

#define LDSM4(r0, r1, r2, r3, a) \
  asm volatile("ldmatrix.sync.aligned.m8n8.x4.shared.b16 {%0,%1,%2,%3}, [%4];" \
               : "=r"(r0), "=r"(r1), "=r"(r2), "=r"(r3) : "r"(a))

#define MMAH(d, a, b0, b1) \
  asm volatile("mma.sync.aligned.m16n8k16.row.col.f32.f16.f16.f32 " \
               "{%0,%1,%2,%3}, {%4,%5,%6,%7}, {%8,%9}, {%0,%1,%2,%3};" \
               : "+f"((d)[0]), "+f"((d)[1]), "+f"((d)[2]), "+f"((d)[3]) \
               : "r"((a)[0]), "r"((a)[1]), "r"((a)[2]), "r"((a)[3]), "r"(b0), "r"(b1))

__device__ __forceinline__ void split2h(float a, float b, uint32_t& hi, uint32_t& lo) {
  __half ha = __float2half_rn(a), hb = __float2half_rn(b);
  __half la = __float2half_rn(a - __half2float(ha));
  __half lb = __float2half_rn(b - __half2float(hb));
  __half2 H(ha, hb), L(la, lb);
  hi = *(uint32_t*)&H;
  lo = *(uint32_t*)&L;
}

// ---------------- prep kernels ----------------
__global__ void zero_state_kernel() {
  int i = blockIdx.x * blockDim.x + threadIdx.x;
  int stride = gridDim.x * blockDim.x;
  for (int k = i; k < BB * NG; k += stride) { d_va[k] = 0.0f; d_zp[k] = 0.0f; }
  if (blockIdx.x == 0 && threadIdx.x < 32) d_cnt[threadIdx.x] = 0;
}

__global__ void convert_whh(const float* __restrict__ W) {
  int i = blockIdx.x * blockDim.x + threadIdx.x;
  int stride = gridDim.x * blockDim.x;
  for (; i < NG * NG / 8; i += stride) {
    int n = i >> 9, k = (i & 511) << 3;
    const float4* s = (const float4*)(W + (long)n * NG + k);
    float4 x = s[0], y = s[1];
    __half2 h0(__float2half_rn(x.x), __float2half_rn(x.y));
    __half2 h1(__float2half_rn(x.z), __float2half_rn(x.w));
    __half2 h2(__float2half_rn(y.x), __float2half_rn(y.y));
    __half2 h3(__float2half_rn(y.z), __float2half_rn(y.w));
    uint4 u = make_uint4(*(uint32_t*)&h0, *(uint32_t*)&h1, *(uint32_t*)&h2, *(uint32_t*)&h3);
    int by = k >> 10, sg = (k & 1023) >> 6, ch = (k & 63) >> 3;
    int bx = n >> 7, r = n & 127;
    long off = (long)((by * 32 + bx) * 16 + sg) * 16384 + r * 128 + ((ch ^ (r & 7)) << 4);
    *(uint4*)(d_wtile + off) = u;
  }
}

__global__ void convert_wdec(const float* __restrict__ W) {
  int i = blockIdx.x * blockDim.x + threadIdx.x;
  int stride = gridDim.x * blockDim.x;
  for (; i < NP * NG / 8; i += stride) {
    int n = i >> 9, k = (i & 511) << 3;
    const float4* s = (const float4*)(W + (long)n * NG + k);
    float4 x = s[0], y = s[1];
    __half2 h0(__float2half_rn(x.x), __float2half_rn(x.y));
    __half2 h1(__float2half_rn(x.z), __float2half_rn(x.w));
    __half2 h2(__float2half_rn(y.x), __float2half_rn(y.y));
    __half2 h3(__float2half_rn(y.z), __float2half_rn(y.w));
    uint4 u = make_uint4(*(uint32_t*)&h0, *(uint32_t*)&h1, *(uint32_t*)&h2, *(uint32_t*)&h3);
    int nx = n >> 6, rn = n & 63;
    int kt = k >> 6, ch = (k & 63) >> 3;
    long off = (long)(nx * 64 + kt) * 8192 + rn * 128 + ((ch ^ (rn & 7)) << 4);
    *(uint4*)(d_wdtile + off) = u;
  }
}

// h0 = p0 @ W_init^T  -> A-slab parity 0 (fp16 hi|lo, tiled/swizzled)
__global__ void h0_kernel(const float* __restrict__ p0, const float* __restrict__ Wi) {
  __shared__ __align__(16) float hs[32][68];
  __shared__ __align__(16) float ws[32][34];
  const int tid = threadIdx.x;
  const int tx = tid & 15, ty = tid >> 4, lk = tid & 31, lr = tid >> 5;
  const int nb = blockIdx.x * 32;
  float acc[4][2];
#pragma unroll
  for (int i = 0; i < 4; i++) { acc[i][0] = 0.f; acc[i][1] = 0.f; }
  float rh[8], rw[4];
#pragma unroll
  for (int i = 0; i < 8; i++) rh[i] = p0[(lr + 8 * i) * NP + lk];
#pragma unroll
  for (int i = 0; i < 4; i++) rw[i] = Wi[(nb + lr + 8 * i) * NP + lk];
  for (int k0 = 0; k0 < NP; k0 += 32) {
#pragma unroll
    for (int i = 0; i < 8; i++) hs[lk][lr + 8 * i] = rh[i];
#pragma unroll
    for (int i = 0; i < 4; i++) ws[lk][lr + 8 * i] = rw[i];
    __syncthreads();
    int k1 = k0 + 32;
    if (k1 < NP) {
#pragma unroll
      for (int i = 0; i < 8; i++) rh[i] = p0[(lr + 8 * i) * NP + k1 + lk];
#pragma unroll
      for (int i = 0; i < 4; i++) rw[i] = Wi[(nb + lr + 8 * i) * NP + k1 + lk];
    }
#pragma unroll
    for (int k = 0; k < 32; k++) {
      float4 hv = *(const float4*)&hs[k][ty * 4];
      float2 wv = *(const float2*)&ws[k][tx * 2];
      acc[0][0] += hv.x * wv.x; acc[0][1] += hv.x * wv.y;
      acc[1][0] += hv.y * wv.x; acc[1][1] += hv.y * wv.y;
      acc[2][0] += hv.z * wv.x; acc[2][1] += hv.z * wv.y;
      acc[3][0] += hv.w * wv.x; acc[3][1] += hv.w * wv.y;
    }
    __syncthreads();
  }
  const int m0 = ty * 4;
  const int n0 = nb + tx * 2;
  const int byn = n0 >> 10, sn = (n0 & 1023) >> 6, ch = (n0 & 63) >> 3;
#pragma unroll
  for (int i = 0; i < 4; i++) {
    uint32_t hi, lo;
    split2h(acc[i][0], acc[i][1], hi, lo);
    int m = m0 + i;
    long off = (long)(byn * 16 + sn) * 16384 + m * 128 + ((ch ^ (m & 7)) << 4) + (n0 & 7) * 2;
    *(uint32_t*)(d_aslab + off) = hi;
    *(uint32_t*)(d_aslab + off + 8192) = lo;
  }
}

// ---------------- step kernel ----------------
// grid (32, 4): bx = n-tile (128 cols), by = k-chunk (1024).
// ALL CTAs write fp32 partials; each reduces its own 32-col quarter + epilogue.
// 8 warps, warp tile 32x32 (2m x 4n); 2 MMA passes; DOUBLE-BUFFERED fragments.
__global__ void __launch_bounds__(256, 1) step_kernel(
    const float* __restrict__ v, const float* __restrict__ Wih, int t) {
  extern __shared__ __align__(1024) char smem[];
  const uint32_t sb = smem_u32(smem);
  const uint32_t mb = sb;
  const uint32_t buf = sb + 1024;
  const int tid = threadIdx.x;
  const int bx = blockIdx.x, by = blockIdx.y;
  const int nb = bx * 128;

  if (tid == 0) {
#pragma unroll
    for (int i = 0; i < 3; i++) MBAR_INIT(mb + 8 * i, 1);
  }
  __syncthreads();

  const ull wbase = (ull)__cvta_generic_to_global(d_wtile) +
                    (ull)((by * 32 + bx) * 16) * 16384ull;
  const ull abase = (ull)__cvta_generic_to_global(d_aslab) +
                    (ull)(((t & 1) * 4 + by) * 16) * 16384ull;

  auto issue = [&](int s) {
    const int slot = s % 3;
    const uint32_t st = buf + (uint32_t)slot * STG_BYTES;
    const uint32_t m = mb + slot * 8;
    MBAR_EXPECT_TX(m, STG_BYTES);
    BULK_G2S(st + OW, wbase + (ull)s * 32768ull, 32768u, m);
    BULK_G2S(st + OA, abase + (ull)s * 32768ull, 32768u, m);
  };
  if (tid == 0) { issue(0); issue(1); }

  const int lane = tid & 31, warp = tid >> 5;
  const int wm = warp & 1, wn = warp >> 1;          // 2m x 4n warps
  const int mA0 = wm * 32 + (lane & 15);            // < 64
  const int nB0 = wn * 32 + (lane & 15);            // < 128
  const int halfk = lane >> 4;
  const uint32_t aA0 = (uint32_t)mA0 * 128, aA1 = aA0 + 16 * 128;
  const uint32_t aB0 = (uint32_t)nB0 * 128, aB1 = aB0 + 16 * 128;
  const uint32_t swA = (uint32_t)(mA0 & 7), swB = (uint32_t)(nB0 & 7);

  float acc[2][4][4];
#pragma unroll
  for (int mi = 0; mi < 2; mi++)
#pragma unroll
    for (int sl = 0; sl < 4; sl++)
#pragma unroll
      for (int f = 0; f < 4; f++) acc[mi][sl][f] = 0.0f;

  // double-buffered fragments
  uint32_t fAh[2][2][4], fAl[2][2][4], fW[2][2][4];

  auto load_frag = [&](int b, uint32_t st, int k16) {
    const uint32_t sub = (uint32_t)(k16 >> 2) * 16384u;
    const uint32_t ch = (uint32_t)((k16 & 3) * 2 + halfk);
    const uint32_t xoA = (ch ^ swA) << 4;
    const uint32_t xoB = (ch ^ swB) << 4;
    LDSM4(fAh[b][0][0], fAh[b][0][1], fAh[b][0][2], fAh[b][0][3], st + OA + sub + aA0 + xoA);
    LDSM4(fAh[b][1][0], fAh[b][1][1], fAh[b][1][2], fAh[b][1][3], st + OA + sub + aA1 + xoA);
    LDSM4(fAl[b][0][0], fAl[b][0][1], fAl[b][0][2], fAl[b][0][3], st + OA + sub + 8192 + aA0 + xoA);
    LDSM4(fAl[b][1][0], fAl[b][1][1], fAl[b][1][2], fAl[b][1][3], st + OA + sub + 8192 + aA1 + xoA);
    LDSM4(fW[b][0][0], fW[b][0][1], fW[b][0][2], fW[b][0][3], st + OW + sub + aB0 + xoB);
    LDSM4(fW[b][1][0], fW[b][1][1], fW[b][1][2], fW[b][1][3], st + OW + sub + aB1 + xoB);
  };

  for (int s = 0; s < NSTG; s++) {
    mbar_wait(mb + (s % 3) * 8, (uint32_t)((s / 3) & 1));
    const uint32_t st = buf + (uint32_t)(s % 3) * STG_BYTES;
    load_frag(0, st, 0);
#pragma unroll
    for (int k16 = 0; k16 < 8; k16++) {
      const int b = k16 & 1;
      if (k16 + 1 < 8) load_frag(b ^ 1, st, k16 + 1);
#pragma unroll
      for (int mi = 0; mi < 2; mi++)
#pragma unroll
        for (int bb = 0; bb < 2; bb++)
#pragma unroll
          for (int j = 0; j < 2; j++)
            MMAH(acc[mi][bb * 2 + j], fAh[b][mi], fW[b][bb][j], fW[b][bb][j + 2]);
#pragma unroll
      for (int mi = 0; mi < 2; mi++)
#pragma unroll
        for (int bb = 0; bb < 2; bb++)
#pragma unroll
          for (int j = 0; j < 2; j++)
            MMAH(acc[mi][bb * 2 + j], fAl[b][mi], fW[b][bb][j], fW[b][bb][j + 2]);
    }
    __syncthreads();
    if (tid == 0 && s + 2 < NSTG) issue(s + 2);
  }

  // ---- write own partial slab (all CTAs) ----
  const int r_ = lane >> 2, c_ = (lane & 3) * 2;
  {
#pragma unroll
    for (int mi = 0; mi < 2; mi++)
#pragma unroll
      for (int bb = 0; bb < 2; bb++)
#pragma unroll
        for (int j = 0; j < 2; j++)
#pragma unroll
          for (int rr = 0; rr < 2; rr++) {
            int m = wm * 32 + mi * 16 + r_ + rr * 8;
            int n = nb + wn * 32 + bb * 16 + j * 8 + c_;
            *(float2*)&d_part[(long)by * (BB * NG) + m * NG + n] =
                make_float2(acc[mi][bb * 2 + j][rr * 2], acc[mi][bb * 2 + j][rr * 2 + 1]);
          }
  }
  __threadfence();
  __syncthreads();
  if (tid == 0) {
    atomicAdd(&d_cnt[bx], 1);
    while (atomicAdd(&d_cnt[bx], 0) < 4 * (t + 1)) __nanosleep(32);
  }
  __syncthreads();
  __threadfence();

  // ---- distributed reduction + RNN epilogue: this CTA owns 32 cols ----
  {
    const float2* wih2 = (const float2*)Wih;
    const int p1 = (t + 1) & 1;
    const int nq = nb + by * 32;
#pragma unroll
    for (int p = 0; p < 4; p++) {
      const int m = warp * 8 + p * 2 + (lane >> 4);
      const int n0 = nq + (lane & 15) * 2;
      const int idx = m * NG + n0;
      float2 q0 = *(const float2*)&d_part[idx];
      float2 q1 = *(const float2*)&d_part[(long)BB * NG + idx];
      float2 q2 = *(const float2*)&d_part[2l * BB * NG + idx];
      float2 q3 = *(const float2*)&d_part[3l * BB * NG + idx];
      const float v0 = v[(m * TT + t) * 2 + 0];
      const float v1 = v[(m * TT + t) * 2 + 1];
      float2 w0 = wih2[n0], w1 = wih2[n0 + 1];
      float z0 = ((q0.x + q1.x) + q2.x) + q3.x + v0 * w0.x + v1 * w0.y;
      float z1 = ((q0.y + q1.y) + q2.y) + q3.y + v0 * w1.x + v1 * w1.y;
      float2 va = *(const float2*)&d_va[idx];
      float2 zp = *(const float2*)&d_zp[idx];
      z0 -= 0.1f * va.x;
      z1 -= 0.1f * va.y;
      *(float2*)&d_va[idx] = make_float2(va.x + 0.9f * (zp.x - va.x),
                                         va.y + 0.9f * (zp.y - va.y));
      *(float2*)&d_zp[idx] = make_float2(z0, z1);
      float s0 = fmaxf(z0, 0.0f), s1 = fmaxf(z1, 0.0f);
      uint32_t hi, lo;
      split2h(s0, s1, hi, lo);
      const int m_dec = m * TT + t;
      const int mt = m_dec >> 7, rdec = m_dec & 127;
      const int kt = n0 >> 6, chn = (n0 & 63) >> 3;
      long goff = (long)(mt * 64 + kt) * 32768 + rdec * 128 +
                  ((chn ^ (rdec & 7)) << 4) + (n0 & 7) * 2;
      *(uint32_t*)(d_gslab + goff) = hi;
      *(uint32_t*)(d_gslab + goff + 16384) = lo;
      const int byn = n0 >> 10, sn = (n0 & 1023) >> 6;
      long off = (long)((p1 * 4 + byn) * 16 + sn) * 16384 + m * 128 +
                 ((chn ^ (m & 7)) << 4) + (n0 & 7) * 2;
      *(uint32_t*)(d_aslab + off) = hi;
      *(uint32_t*)(d_aslab + off + 8192) = lo;
    }
  }
}

// ---------------- decode: bulk-fed pipeline, double-buffered fragments ----------------
__global__ void __launch_bounds__(256, 1) decode_gemm(float* __restrict__ outp) {
  extern __shared__ __align__(1024) char smem[];
  const uint32_t sb = smem_u32(smem);
  const uint32_t mb = sb;
  const uint32_t buf = sb + 1024;
  const int tid = threadIdx.x;
  const int nx = blockIdx.x, mt = blockIdx.y;

  if (tid == 0) {
#pragma unroll
    for (int i = 0; i < 4; i++) MBAR_INIT(mb + 8 * i, 1);
  }
  __syncthreads();

  const ull gbase = (ull)__cvta_generic_to_global(d_gslab) + (ull)(mt * 64) * 32768ull;
  const ull wbase = (ull)__cvta_generic_to_global(d_wdtile) + (ull)(nx * 64) * 8192ull;

  auto issue = [&](int s) {
    const uint32_t st = buf + (uint32_t)(s & 3) * DSTG;
    const uint32_t m = mb + (s & 3) * 8;
    MBAR_EXPECT_TX(m, DSTG);
    BULK_G2S(st + D_OAH, gbase + (ull)s * 32768ull, 32768u, m);
    BULK_G2S(st + D_OWH, wbase + (ull)s * 8192ull, 8192u, m);
  };
  if (tid == 0) { issue(0); issue(1); issue(2); }

  const int lane = tid & 31, warp = tid >> 5;
  const int wm = warp & 3, wn = warp >> 2;
  const int mA0 = wm * 32 + (lane & 15);
  const int nB0 = wn * 32 + (lane & 15);
  const int halfk = lane >> 4;
  const uint32_t aA0 = (uint32_t)mA0 * 128, aA1 = aA0 + 16 * 128;
  const uint32_t aB0 = (uint32_t)nB0 * 128, aB1 = aB0 + 16 * 128;
  const uint32_t swA = (uint32_t)(mA0 & 7), swB = (uint32_t)(nB0 & 7);

  float acc[2][4][4];
#pragma unroll
  for (int mi = 0; mi < 2; mi++)
#pragma unroll
    for (int sl = 0; sl < 4; sl++)
#pragma unroll
      for (int f = 0; f < 4; f++) acc[mi][sl][f] = 0.0f;

  uint32_t fAh[2][2][4], fAl[2][2][4], fW[2][2][4];
  auto load_frag = [&](int b, uint32_t st, int k16) {
    const uint32_t ch = (uint32_t)(k16 * 2 + halfk);
    const uint32_t xoA = (ch ^ swA) << 4;
    const uint32_t xoB = (ch ^ swB) << 4;
    LDSM4(fAh[b][0][0], fAh[b][0][1], fAh[b][0][2], fAh[b][0][3], st + D_OAH + aA0 + xoA);
    LDSM4(fAh[b][1][0], fAh[b][1][1], fAh[b][1][2], fAh[b][1][3], st + D_OAH + aA1 + xoA);
    LDSM4(fAl[b][0][0], fAl[b][0][1], fAl[b][0][2], fAl[b][0][3], st + D_OAL + aA0 + xoA);
    LDSM4(fAl[b][1][0], fAl[b][1][1], fAl[b][1][2], fAl[b][1][3], st + D_OAL + aA1 + xoA);
    LDSM4(fW[b][0][0], fW[b][0][1], fW[b][0][2], fW[b][0][3], st + D_OWH + aB0 + xoB);
    LDSM4(fW[b][1][0], fW[b][1][1], fW[b][1][2], fW[b][1][3], st + D_OWH + aB1 + xoB);
  };

  for (int s = 0; s < 64; s++) {
    mbar_wait(mb + (s & 3) * 8, (uint32_t)((s >> 2) & 1));
    const uint32_t st = buf + (uint32_t)(s & 3) * DSTG;
    load_frag(0, st, 0);
#pragma unroll
    for (int k16 = 0; k16 < 4; k16++) {
      const int b = k16 & 1;
      if (k16 + 1 < 4) load_frag(b ^ 1, st, k16 + 1);
#pragma unroll
      for (int mi = 0; mi < 2; mi++)
#pragma unroll
        for (int bb = 0; bb < 2; bb++)
#pragma unroll
          for (int j = 0; j < 2; j++)
            MMAH(acc[mi][bb * 2 + j], fAh[b][mi], fW[b][bb][j], fW[b][bb][j + 2]);
#pragma unroll
      for (int mi = 0; mi < 2; mi++)
#pragma unroll
        for (int bb = 0; bb < 2; bb++)
#pragma unroll
          for (int j = 0; j < 2; j++)
            MMAH(acc[mi][bb * 2 + j], fAl[b][mi], fW[b][bb][j], fW[b][bb][j + 2]);
    }
    __syncthreads();
    if (tid == 0 && s + 3 < 64) issue(s + 3);
  }

  const int r_ = lane >> 2, c_ = (lane & 3) * 2;
#pragma unroll
  for (int mi = 0; mi < 2; mi++)
#pragma unroll
    for (int bb = 0; bb < 2; bb++)
#pragma unroll
      for (int j = 0; j < 2; j++)
#pragma unroll
        for (int rr = 0; rr < 2; rr++) {
          long m = (long)mt * 128 + wm * 32 + mi * 16 + r_ + rr * 8;
          int n = nx * 64 + wn * 32 + bb * 16 + j * 8 + c_;
          *(float2*)&outp[m * NP + n] =
              make_float2(acc[mi][bb * 2 + j][rr * 2], acc[mi][bb * 2 + j][rr * 2 + 1]);
        }
}

// ---------------- launch ----------------
extern "C" void kernel_launch(void* const* d_in, const int* in_sizes, int n_in,
                              void* d_out, int out_size) {
  const float* v      = (const float*)d_in[0];
  const float* p0     = (const float*)d_in[1];
  const float* W_init = (const float*)d_in[2];
  const float* W_ih   = (const float*)d_in[3];
  const float* W_hh   = (const float*)d_in[4];
  const float* W_dec  = (const float*)d_in[5];
  float* out = (float*)d_out;

  cudaFuncSetAttribute(step_kernel, cudaFuncAttributeMaxDynamicSharedMemorySize, SMEM_STEP);
  cudaFuncSetAttribute(decode_gemm, cudaFuncAttributeMaxDynamicSharedMemorySize, SMEM_DEC);

  convert_whh<<<2048, 256>>>(W_hh);
  convert_wdec<<<256, 256>>>(W_dec);
  zero_state_kernel<<<128, 256>>>();
  h0_kernel<<<128, 256>>>(p0, W_init);

  for (int t = 0; t < TT; t++)
    step_kernel<<<dim3(32, 4), 256, SMEM_STEP>>>(v, W_ih, t);

  decode_gemm<<<dim3(8, 50), 256, SMEM_DEC>>>(out);
}

// round 17
// speedup vs baseline: 1.1258x; 1.0198x over previous
#include <cuda_runtime.h>
#include <cuda_bf16.h>
#include <cuda_fp16.h>
#include <cstdint>

// SorscherRNN on mma.sync, fp16 asymmetric split (A hi+lo fp16, W single fp16).
// R17: persistent step kernel with FINE-GRAINED per-stage A gating:
//  - stage s of step t+1 depends only on the 4 CTAs with bx = 8*by+s; gate each
//    stage's A issue on ecnt[8*by+s] >= 4*t (in-loop) instead of a full barrier.
//  - boundary: after own epilogue, wait only stages 0,1 gates; W ungated.
//  - A-slab 4-deep ring + partials double-buffered (skew < 2 steps by
//    two-hop transitive counter dependency) -> race-free.
// Distributed 4-way reduction + fragment double-buffering kept from R16.

#define NG 4096
#define NP 512
#define BB 64
#define TT 100

#define NSTG 8
#define STG_BYTES 65536u
#define OW 0u
#define OA 32768u
#define SMEM_STEP (1024 + 3 * 65536)

#define DSTG 40960u
#define D_OAH 0u
#define D_OAL 16384u
#define D_OWH 32768u
#define SMEM_DEC (1024 + 4 * 40960)

typedef unsigned long long ull;

// ---------------- device scratch (allocation-free) ----------------
__device__ __align__(16) unsigned char d_wtile[4ull * 32 * 16 * 16384];  // 32MB W_hh fp16 tiled
__device__ __align__(16) unsigned char d_aslab[4ull * 4 * 16 * 16384];   // 4MB A hi|lo, 4-deep ring
__device__ __align__(16) unsigned char d_gslab[50ull * 64 * 32768];      // 100MB g hi|lo tiled
__device__ __align__(16) unsigned char d_wdtile[8ull * 64 * 8192];       // 4MB W_dec fp16 tiled
__device__ float d_va[BB * NG], d_zp[BB * NG];
__device__ float d_part[2ull * 4 * BB * NG];  // split-K partials, double-buffered
__device__ int d_cnt[64];  // [0..31]=pcnt(partials), [32..63]=ecnt(A published); monotonic

// ---------------- helpers ----------------
__device__ __forceinline__ uint32_t smem_u32(const void* p) {
  uint32_t a;
  asm("{ .reg .u64 t; cvta.to.shared.u64 t, %1; cvt.u32.u64 %0, t; }" : "=r"(a) : "l"(p));
  return a;
}

#define MBAR_INIT(a, c) asm volatile("mbarrier.init.shared.b64 [%0], %1;" :: "r"(a), "r"(c) : "memory")
#define MBAR_EXPECT_TX(a, n) \
  asm volatile("mbarrier.arrive.expect_tx.shared.b64 _, [%0], %1;" :: "r"(a), "r"(n) : "memory")
__device__ __forceinline__ void mbar_wait(uint32_t a, uint32_t par) {
  asm volatile(
      "{ .reg .pred P;\n"
      "WL%=: mbarrier.try_wait.parity.acquire.cta.shared::cta.b64 P, [%0], %1, 0x989680;\n"
      "@P bra WD%=;\n"
      "bra WL%=;\n"
      "WD%=: }"
      :: "r"(a), "r"(par) : "memory");
}
#define BULK_G2S(dst, src, sz, mb) \
  asm volatile("cp.async.bulk.shared::cta.global.mbarrier::complete_tx::bytes [%0], [%1], %2, [%3];" \
               :: "r"(dst), "l"(src), "r"(sz), "r"(mb) : "memory")

#define LDSM4(r0, r1, r2, r3, a) \
  asm volatile("ldmatrix.sync.aligned.m8n8.x4.shared.b16 {%0,%1,%2,%3}, [%4];" \
               : "=r"(r0), "=r"(r1), "=r"(r2), "=r"(r3) : "r"(a))

#define MMAH(d, a, b0, b1) \
  asm volatile("mma.sync.aligned.m16n8k16.row.col.f32.f16.f16.f32 " \
               "{%0,%1,%2,%3}, {%4,%5,%6,%7}, {%8,%9}, {%0,%1,%2,%3};" \
               : "+f"((d)[0]), "+f"((d)[1]), "+f"((d)[2]), "+f"((d)[3]) \
               : "r"((a)[0]), "r"((a)[1]), "r"((a)[2]), "r"((a)[3]), "r"(b0), "r"(b1))

__device__ __forceinline__ void split2h(float a, float b, uint32_t& hi, uint32_t& lo) {
  __half ha = __float2half_rn(a), hb = __float2half_rn(b);
  __half la = __float2half_rn(a - __half2float(ha));
  __half lb = __float2half_rn(b - __half2float(hb));
  __half2 H(ha, hb), L(la, lb);
  hi = *(uint32_t*)&H;
  lo = *(uint32_t*)&L;
}

// ---------------- prep kernels ----------------
__global__ void zero_state_kernel() {
  int i = blockIdx.x * blockDim.x + threadIdx.x;
  int stride = gridDim.x * blockDim.x;
  for (int k = i; k < BB * NG; k += stride) { d_va[k] = 0.0f; d_zp[k] = 0.0f; }
  if (blockIdx.x == 0 && threadIdx.x < 64) d_cnt[threadIdx.x] = 0;
}

__global__ void convert_whh(const float* __restrict__ W) {
  int i = blockIdx.x * blockDim.x + threadIdx.x;
  int stride = gridDim.x * blockDim.x;
  for (; i < NG * NG / 8; i += stride) {
    int n = i >> 9, k = (i & 511) << 3;
    const float4* s = (const float4*)(W + (long)n * NG + k);
    float4 x = s[0], y = s[1];
    __half2 h0(__float2half_rn(x.x), __float2half_rn(x.y));
    __half2 h1(__float2half_rn(x.z), __float2half_rn(x.w));
    __half2 h2(__float2half_rn(y.x), __float2half_rn(y.y));
    __half2 h3(__float2half_rn(y.z), __float2half_rn(y.w));
    uint4 u = make_uint4(*(uint32_t*)&h0, *(uint32_t*)&h1, *(uint32_t*)&h2, *(uint32_t*)&h3);
    int by = k >> 10, sg = (k & 1023) >> 6, ch = (k & 63) >> 3;
    int bx = n >> 7, r = n & 127;
    long off = (long)((by * 32 + bx) * 16 + sg) * 16384 + r * 128 + ((ch ^ (r & 7)) << 4);
    *(uint4*)(d_wtile + off) = u;
  }
}

__global__ void convert_wdec(const float* __restrict__ W) {
  int i = blockIdx.x * blockDim.x + threadIdx.x;
  int stride = gridDim.x * blockDim.x;
  for (; i < NP * NG / 8; i += stride) {
    int n = i >> 9, k = (i & 511) << 3;
    const float4* s = (const float4*)(W + (long)n * NG + k);
    float4 x = s[0], y = s[1];
    __half2 h0(__float2half_rn(x.x), __float2half_rn(x.y));
    __half2 h1(__float2half_rn(x.z), __float2half_rn(x.w));
    __half2 h2(__float2half_rn(y.x), __float2half_rn(y.y));
    __half2 h3(__float2half_rn(y.z), __float2half_rn(y.w));
    uint4 u = make_uint4(*(uint32_t*)&h0, *(uint32_t*)&h1, *(uint32_t*)&h2, *(uint32_t*)&h3);
    int nx = n >> 6, rn = n & 63;
    int kt = k >> 6, ch = (k & 63) >> 3;
    long off = (long)(nx * 64 + kt) * 8192 + rn * 128 + ((ch ^ (rn & 7)) << 4);
    *(uint4*)(d_wdtile + off) = u;
  }
}

// h0 = p0 @ W_init^T  -> A-slab ring slot 0 (fp16 hi|lo, tiled/swizzled)
__global__ void h0_kernel(const float* __restrict__ p0, const float* __restrict__ Wi) {
  __shared__ __align__(16) float hs[32][68];
  __shared__ __align__(16) float ws[32][34];
  const int tid = threadIdx.x;
  const int tx = tid & 15, ty = tid >> 4, lk = tid & 31, lr = tid >> 5;
  const int nb = blockIdx.x * 32;
  float acc[4][2];
#pragma unroll
  for (int i = 0; i < 4; i++) { acc[i][0] = 0.f; acc[i][1] = 0.f; }
  float rh[8], rw[4];
#pragma unroll
  for (int i = 0; i < 8; i++) rh[i] = p0[(lr + 8 * i) * NP + lk];
#pragma unroll
  for (int i = 0; i < 4; i++) rw[i] = Wi[(nb + lr + 8 * i) * NP + lk];
  for (int k0 = 0; k0 < NP; k0 += 32) {
#pragma unroll
    for (int i = 0; i < 8; i++) hs[lk][lr + 8 * i] = rh[i];
#pragma unroll
    for (int i = 0; i < 4; i++) ws[lk][lr + 8 * i] = rw[i];
    __syncthreads();
    int k1 = k0 + 32;
    if (k1 < NP) {
#pragma unroll
      for (int i = 0; i < 8; i++) rh[i] = p0[(lr + 8 * i) * NP + k1 + lk];
#pragma unroll
      for (int i = 0; i < 4; i++) rw[i] = Wi[(nb + lr + 8 * i) * NP + k1 + lk];
    }
#pragma unroll
    for (int k = 0; k < 32; k++) {
      float4 hv = *(const float4*)&hs[k][ty * 4];
      float2 wv = *(const float2*)&ws[k][tx * 2];
      acc[0][0] += hv.x * wv.x; acc[0][1] += hv.x * wv.y;
      acc[1][0] += hv.y * wv.x; acc[1][1] += hv.y * wv.y;
      acc[2][0] += hv.z * wv.x; acc[2][1] += hv.z * wv.y;
      acc[3][0] += hv.w * wv.x; acc[3][1] += hv.w * wv.y;
    }
    __syncthreads();
  }
  const int m0 = ty * 4;
  const int n0 = nb + tx * 2;
  const int byn = n0 >> 10, sn = (n0 & 1023) >> 6, ch = (n0 & 63) >> 3;
#pragma unroll
  for (int i = 0; i < 4; i++) {
    uint32_t hi, lo;
    split2h(acc[i][0], acc[i][1], hi, lo);
    int m = m0 + i;
    long off = (long)(byn * 16 + sn) * 16384 + m * 128 + ((ch ^ (m & 7)) << 4) + (n0 & 7) * 2;
    *(uint32_t*)(d_aslab + off) = hi;
    *(uint32_t*)(d_aslab + off + 8192) = lo;
  }
}

// ---------------- persistent step kernel: all 100 steps ----------------
// grid (32, 4): bx = n-tile (128 cols), by = k-chunk (1024).
__global__ void __launch_bounds__(256, 1) rnn_persistent(
    const float* __restrict__ v, const float* __restrict__ Wih) {
  extern __shared__ __align__(1024) char smem[];
  const uint32_t sb = smem_u32(smem);
  const uint32_t mb = sb;
  const uint32_t buf = sb + 1024;
  const int tid = threadIdx.x;
  const int bx = blockIdx.x, by = blockIdx.y;
  const int nb = bx * 128;

  if (tid == 0) {
#pragma unroll
    for (int i = 0; i < 3; i++) MBAR_INIT(mb + 8 * i, 2);  // 2 arrivals: W + A expect_tx
  }
  __syncthreads();

  const ull wbase = (ull)__cvta_generic_to_global(d_wtile) +
                    (ull)((by * 32 + bx) * 16) * 16384ull;
  const ull aslab = (ull)__cvta_generic_to_global(d_aslab);

  auto issueW = [&](int sg) {
    const int slot = sg % 3;
    const uint32_t m = mb + slot * 8;
    MBAR_EXPECT_TX(m, 32768u);
    BULK_G2S(buf + (uint32_t)slot * STG_BYTES + OW,
             wbase + (ull)(sg & 7) * 32768ull, 32768u, m);
  };
  auto issueA = [&](int sg) {
    const int slot = sg % 3;
    const int t = sg >> 3, s = sg & 7;
    const uint32_t m = mb + slot * 8;
    const ull abase = aslab + (ull)(((t & 3) * 4 + by) * 16) * 16384ull;
    MBAR_EXPECT_TX(m, 32768u);
    BULK_G2S(buf + (uint32_t)slot * STG_BYTES + OA,
             abase + (ull)s * 32768ull, 32768u, m);
  };

  if (tid == 0) { issueW(0); issueA(0); issueW(1); issueA(1); }

  const int lane = tid & 31, warp = tid >> 5;
  const int wm = warp & 1, wn = warp >> 1;          // 2m x 4n warps
  const int mA0 = wm * 32 + (lane & 15);
  const int nB0 = wn * 32 + (lane & 15);
  const int halfk = lane >> 4;
  const uint32_t aA0 = (uint32_t)mA0 * 128, aA1 = aA0 + 16 * 128;
  const uint32_t aB0 = (uint32_t)nB0 * 128, aB1 = aB0 + 16 * 128;
  const uint32_t swA = (uint32_t)(mA0 & 7), swB = (uint32_t)(nB0 & 7);
  const int r_ = lane >> 2, c_ = (lane & 3) * 2;
  const float2* wih2 = (const float2*)Wih;

  uint32_t fAh[2][2][4], fAl[2][2][4], fW[2][2][4];
  auto load_frag = [&](int b, uint32_t st, int k16) {
    const uint32_t sub = (uint32_t)(k16 >> 2) * 16384u;
    const uint32_t ch = (uint32_t)((k16 & 3) * 2 + halfk);
    const uint32_t xoA = (ch ^ swA) << 4;
    const uint32_t xoB = (ch ^ swB) << 4;
    LDSM4(fAh[b][0][0], fAh[b][0][1], fAh[b][0][2], fAh[b][0][3], st + OA + sub + aA0 + xoA);
    LDSM4(fAh[b][1][0], fAh[b][1][1], fAh[b][1][2], fAh[b][1][3], st + OA + sub + aA1 + xoA);
    LDSM4(fAl[b][0][0], fAl[b][0][1], fAl[b][0][2], fAl[b][0][3], st + OA + sub + 8192 + aA0 + xoA);
    LDSM4(fAl[b][1][0], fAl[b][1][1], fAl[b][1][2], fAl[b][1][3], st + OA + sub + 8192 + aA1 + xoA);
    LDSM4(fW[b][0][0], fW[b][0][1], fW[b][0][2], fW[b][0][3], st + OW + sub + aB0 + xoB);
    LDSM4(fW[b][1][0], fW[b][1][1], fW[b][1][2], fW[b][1][3], st + OW + sub + aB1 + xoB);
  };

  for (int t = 0; t < TT; t++) {
    float acc[2][4][4];
#pragma unroll
    for (int mi = 0; mi < 2; mi++)
#pragma unroll
      for (int sl = 0; sl < 4; sl++)
#pragma unroll
        for (int f = 0; f < 4; f++) acc[mi][sl][f] = 0.0f;

    for (int s = 0; s < NSTG; s++) {
      const int sg = t * 8 + s;
      mbar_wait(mb + (sg % 3) * 8, (uint32_t)((sg / 3) & 1));
      const uint32_t st = buf + (uint32_t)(sg % 3) * STG_BYTES;
      load_frag(0, st, 0);
#pragma unroll
      for (int k16 = 0; k16 < 8; k16++) {
        const int b = k16 & 1;
        if (k16 + 1 < 8) load_frag(b ^ 1, st, k16 + 1);
#pragma unroll
        for (int mi = 0; mi < 2; mi++)
#pragma unroll
          for (int bb = 0; bb < 2; bb++)
#pragma unroll
            for (int j = 0; j < 2; j++)
              MMAH(acc[mi][bb * 2 + j], fAh[b][mi], fW[b][bb][j], fW[b][bb][j + 2]);
#pragma unroll
        for (int mi = 0; mi < 2; mi++)
#pragma unroll
          for (int bb = 0; bb < 2; bb++)
#pragma unroll
            for (int j = 0; j < 2; j++)
              MMAH(acc[mi][bb * 2 + j], fAl[b][mi], fW[b][bb][j], fW[b][bb][j + 2]);
      }
      __syncthreads();
      if (tid == 0) {
        const int sgn = sg + 2;
        if (sgn < TT * 8) {
          issueW(sgn);
          if ((sgn >> 3) == t) {  // same step: gate this stage's A producers (step t-1)
            if (t > 0) {
              while (atomicAdd(&d_cnt[32 + by * 8 + (sgn & 7)], 0) < 4 * t) __nanosleep(32);
            }
            issueA(sgn);
          }  // cross-boundary A deferred to post-epilogue
        }
      }
    }

    // ---- write own partial slab (double-buffered by t&1) ----
    {
      const long pbase = (long)((t & 1) * 4 + by) * (BB * NG);
#pragma unroll
      for (int mi = 0; mi < 2; mi++)
#pragma unroll
        for (int bb = 0; bb < 2; bb++)
#pragma unroll
          for (int j = 0; j < 2; j++)
#pragma unroll
            for (int rr = 0; rr < 2; rr++) {
              int m = wm * 32 + mi * 16 + r_ + rr * 8;
              int n = nb + wn * 32 + bb * 16 + j * 8 + c_;
              *(float2*)&d_part[pbase + m * NG + n] =
                  make_float2(acc[mi][bb * 2 + j][rr * 2], acc[mi][bb * 2 + j][rr * 2 + 1]);
            }
    }
    __threadfence();
    __syncthreads();
    if (tid == 0) {
      atomicAdd(&d_cnt[bx], 1);
      while (atomicAdd(&d_cnt[bx], 0) < 4 * (t + 1)) __nanosleep(32);
    }
    __syncthreads();
    __threadfence();

    // ---- distributed reduction + RNN epilogue: this CTA owns 32 cols ----
    {
      const long pb = (long)(t & 1) * 4 * (BB * NG);
      const int p1 = (t + 1) & 3;  // A-slab ring slot for step t+1
      const int nq = nb + by * 32;
#pragma unroll
      for (int p = 0; p < 4; p++) {
        const int m = warp * 8 + p * 2 + (lane >> 4);
        const int n0 = nq + (lane & 15) * 2;
        const int idx = m * NG + n0;
        float2 q0 = *(const float2*)&d_part[pb + idx];
        float2 q1 = *(const float2*)&d_part[pb + (long)BB * NG + idx];
        float2 q2 = *(const float2*)&d_part[pb + 2l * BB * NG + idx];
        float2 q3 = *(const float2*)&d_part[pb + 3l * BB * NG + idx];
        const float v0 = v[(m * TT + t) * 2 + 0];
        const float v1 = v[(m * TT + t) * 2 + 1];
        float2 w0 = wih2[n0], w1 = wih2[n0 + 1];
        float z0 = ((q0.x + q1.x) + q2.x) + q3.x + v0 * w0.x + v1 * w0.y;
        float z1 = ((q0.y + q1.y) + q2.y) + q3.y + v0 * w1.x + v1 * w1.y;
        float2 va = *(const float2*)&d_va[idx];
        float2 zp = *(const float2*)&d_zp[idx];
        z0 -= 0.1f * va.x;
        z1 -= 0.1f * va.y;
        *(float2*)&d_va[idx] = make_float2(va.x + 0.9f * (zp.x - va.x),
                                           va.y + 0.9f * (zp.y - va.y));
        *(float2*)&d_zp[idx] = make_float2(z0, z1);
        float s0 = fmaxf(z0, 0.0f), s1 = fmaxf(z1, 0.0f);
        uint32_t hi, lo;
        split2h(s0, s1, hi, lo);
        const int m_dec = m * TT + t;
        const int mt = m_dec >> 7, rdec = m_dec & 127;
        const int kt = n0 >> 6, chn = (n0 & 63) >> 3;
        long goff = (long)(mt * 64 + kt) * 32768 + rdec * 128 +
                    ((chn ^ (rdec & 7)) << 4) + (n0 & 7) * 2;
        *(uint32_t*)(d_gslab + goff) = hi;
        *(uint32_t*)(d_gslab + goff + 16384) = lo;
        const int byn = n0 >> 10, sn = (n0 & 1023) >> 6;
        long off = (long)((p1 * 4 + byn) * 16 + sn) * 16384 + m * 128 +
                   ((chn ^ (m & 7)) << 4) + (n0 & 7) * 2;
        *(uint32_t*)(d_aslab + off) = hi;
        *(uint32_t*)(d_aslab + off + 8192) = lo;
      }
    }
    __threadfence();
    __syncthreads();
    if (tid == 0) {
      atomicAdd(&d_cnt[32 + bx], 1);
      if (t + 1 < TT) {
        // fine-grained: only stages 0,1 gates before next step's prologue A
        while (atomicAdd(&d_cnt[32 + by * 8 + 0], 0) < 4 * (t + 1)) __nanosleep(32);
        issueA((t + 1) * 8);
        while (atomicAdd(&d_cnt[32 + by * 8 + 1], 0) < 4 * (t + 1)) __nanosleep(32);
        issueA((t + 1) * 8 + 1);
      }
    }
  }
}

// ---------------- decode: bulk-fed pipeline, double-buffered fragments ----------------
__global__ void __launch_bounds__(256, 1) decode_gemm(float* __restrict__ outp) {
  extern __shared__ __align__(1024) char smem[];
  const uint32_t sb = smem_u32(smem);
  const uint32_t mb = sb;
  const uint32_t buf = sb + 1024;
  const int tid = threadIdx.x;
  const int nx = blockIdx.x, mt = blockIdx.y;

  if (tid == 0) {
#pragma unroll
    for (int i = 0; i < 4; i++) MBAR_INIT(mb + 8 * i, 1);
  }
  __syncthreads();

  const ull gbase = (ull)__cvta_generic_to_global(d_gslab) + (ull)(mt * 64) * 32768ull;
  const ull wbase = (ull)__cvta_generic_to_global(d_wdtile) + (ull)(nx * 64) * 8192ull;

  auto issue = [&](int s) {
    const uint32_t st = buf + (uint32_t)(s & 3) * DSTG;
    const uint32_t m = mb + (s & 3) * 8;
    MBAR_EXPECT_TX(m, DSTG);
    BULK_G2S(st + D_OAH, gbase + (ull)s * 32768ull, 32768u, m);
    BULK_G2S(st + D_OWH, wbase + (ull)s * 8192ull, 8192u, m);
  };
  if (tid == 0) { issue(0); issue(1); issue(2); }

  const int lane = tid & 31, warp = tid >> 5;
  const int wm = warp & 3, wn = warp >> 2;
  const int mA0 = wm * 32 + (lane & 15);
  const int nB0 = wn * 32 + (lane & 15);
  const int halfk = lane >> 4;
  const uint32_t aA0 = (uint32_t)mA0 * 128, aA1 = aA0 + 16 * 128;
  const uint32_t aB0 = (uint32_t)nB0 * 128, aB1 = aB0 + 16 * 128;
  const uint32_t swA = (uint32_t)(mA0 & 7), swB = (uint32_t)(nB0 & 7);

  float acc[2][4][4];
#pragma unroll
  for (int mi = 0; mi < 2; mi++)
#pragma unroll
    for (int sl = 0; sl < 4; sl++)
#pragma unroll
      for (int f = 0; f < 4; f++) acc[mi][sl][f] = 0.0f;

  uint32_t fAh[2][2][4], fAl[2][2][4], fW[2][2][4];
  auto load_frag = [&](int b, uint32_t st, int k16) {
    const uint32_t ch = (uint32_t)(k16 * 2 + halfk);
    const uint32_t xoA = (ch ^ swA) << 4;
    const uint32_t xoB = (ch ^ swB) << 4;
    LDSM4(fAh[b][0][0], fAh[b][0][1], fAh[b][0][2], fAh[b][0][3], st + D_OAH + aA0 + xoA);
    LDSM4(fAh[b][1][0], fAh[b][1][1], fAh[b][1][2], fAh[b][1][3], st + D_OAH + aA1 + xoA);
    LDSM4(fAl[b][0][0], fAl[b][0][1], fAl[b][0][2], fAl[b][0][3], st + D_OAL + aA0 + xoA);
    LDSM4(fAl[b][1][0], fAl[b][1][1], fAl[b][1][2], fAl[b][1][3], st + D_OAL + aA1 + xoA);
    LDSM4(fW[b][0][0], fW[b][0][1], fW[b][0][2], fW[b][0][3], st + D_OWH + aB0 + xoB);
    LDSM4(fW[b][1][0], fW[b][1][1], fW[b][1][2], fW[b][1][3], st + D_OWH + aB1 + xoB);
  };

  for (int s = 0; s < 64; s++) {
    mbar_wait(mb + (s & 3) * 8, (uint32_t)((s >> 2) & 1));
    const uint32_t st = buf + (uint32_t)(s & 3) * DSTG;
    load_frag(0, st, 0);
#pragma unroll
    for (int k16 = 0; k16 < 4; k16++) {
      const int b = k16 & 1;
      if (k16 + 1 < 4) load_frag(b ^ 1, st, k16 + 1);
#pragma unroll
      for (int mi = 0; mi < 2; mi++)
#pragma unroll
        for (int bb = 0; bb < 2; bb++)
#pragma unroll
          for (int j = 0; j < 2; j++)
            MMAH(acc[mi][bb * 2 + j], fAh[b][mi], fW[b][bb][j], fW[b][bb][j + 2]);
#pragma unroll
      for (int mi = 0; mi < 2; mi++)
#pragma unroll
        for (int bb = 0; bb < 2; bb++)
#pragma unroll
          for (int j = 0; j < 2; j++)
            MMAH(acc[mi][bb * 2 + j], fAl[b][mi], fW[b][bb][j], fW[b][bb][j + 2]);
    }
    __syncthreads();
    if (tid == 0 && s + 3 < 64) issue(s + 3);
  }

  const int r_ = lane >> 2, c_ = (lane & 3) * 2;
#pragma unroll
  for (int mi = 0; mi < 2; mi++)
#pragma unroll
    for (int bb = 0; bb < 2; bb++)
#pragma unroll
      for (int j = 0; j < 2; j++)
#pragma unroll
        for (int rr = 0; rr < 2; rr++) {
          long m = (long)mt * 128 + wm * 32 + mi * 16 + r_ + rr * 8;
          int n = nx * 64 + wn * 32 + bb * 16 + j * 8 + c_;
          *(float2*)&outp[m * NP + n] =
              make_float2(acc[mi][bb * 2 + j][rr * 2], acc[mi][bb * 2 + j][rr * 2 + 1]);
        }
}

// ---------------- launch ----------------
extern "C" void kernel_launch(void* const* d_in, const int* in_sizes, int n_in,
                              void* d_out, int out_size) {
  const float* v      = (const float*)d_in[0];
  const float* p0     = (const float*)d_in[1];
  const float* W_init = (const float*)d_in[2];
  const float* W_ih   = (const float*)d_in[3];
  const float* W_hh   = (const float*)d_in[4];
  const float* W_dec  = (const float*)d_in[5];
  float* out = (float*)d_out;

  cudaFuncSetAttribute(rnn_persistent, cudaFuncAttributeMaxDynamicSharedMemorySize, SMEM_STEP);
  cudaFuncSetAttribute(decode_gemm, cudaFuncAttributeMaxDynamicSharedMemorySize, SMEM_DEC);

  convert_whh<<<2048, 256>>>(W_hh);
  convert_wdec<<<256, 256>>>(W_dec);
  zero_state_kernel<<<128, 256>>>();
  h0_kernel<<<128, 256>>>(p0, W_init);

  rnn_persistent<<<dim3(32, 4), 256, SMEM_STEP>>>(v, W_ih);

  decode_gemm<<<dim3(8, 50), 256, SMEM_DEC>>>(out);
}